// round 10
// baseline (speedup 1.0000x reference)
#include <cuda_runtime.h>
#include <cstdint>
#include <cstddef>

#define NNODES 50000
#define NEDGES 800000
#define NREL   8
#define DIM    128
#define KTOT   1152      // 9 chunks of 128
#define KT     32        // k-tile
#define NKT    (KTOT / KT)   // 36
#define LNEPS  1e-5f
#define BM     128

// ---------------- scratch (device globals; no allocation allowed) ----------------
__device__ float g_xA[(size_t)NNODES * DIM];                 // 25.6 MB
__device__ float g_xB[(size_t)NNODES * DIM];                 // 25.6 MB
__device__ float g_agg[(size_t)NNODES * NREL * DIM];         // 204.8 MB
__device__ float g_cnt[(size_t)NNODES * NREL];               // 1.6 MB

// ---------------- utility kernels ----------------
__global__ void zero2_kernel(float4* __restrict__ a, int n4a,
                             float4* __restrict__ c, int n4c) {
    int i = blockIdx.x * blockDim.x + threadIdx.x;
    float4 z = make_float4(0.f, 0.f, 0.f, 0.f);
    if (i < n4a) a[i] = z;
    else if (i - n4a < n4c) c[i - n4a] = z;
}

__global__ void gather_kernel(const int* __restrict__ ids,
                              const float4* __restrict__ emb,
                              float4* __restrict__ x) {
    int i = blockIdx.x * blockDim.x + threadIdx.x;
    if (i >= NNODES * (DIM / 4)) return;
    int row = i >> 5;
    int c   = i & 31;
    x[(size_t)row * 32 + c] = emb[(size_t)ids[row] * 32 + c];
}

// One warp per edge: read 128 floats of x[src] (L2-resident), vector-reduce into agg.
__global__ void scatter_kernel(const float* __restrict__ x,
                               const int* __restrict__ ei,
                               const int* __restrict__ et) {
    int t = blockIdx.x * blockDim.x + threadIdx.x;
    int e = t >> 5;
    if (e >= NEDGES) return;
    int lane = t & 31;
    int src = ei[e];
    int dst = ei[NEDGES + e];
    int r   = et[e];
    size_t seg = (size_t)dst * NREL + r;
    float4 v = *(const float4*)(x + (size_t)src * DIM + lane * 4);
    float* p = g_agg + seg * DIM + lane * 4;
    asm volatile("red.global.add.v4.f32 [%0], {%1,%2,%3,%4};"
                 :: "l"(p), "f"(v.x), "f"(v.y), "f"(v.z), "f"(v.w) : "memory");
    if (lane == 0) atomicAdd(g_cnt + seg, 1.0f);
}

// ---------------- fused RGCN GEMM, pipelined K=1152 ----------------
// out[n,:] = A[n, 0:1152] @ Bcat + bias, A = [agg/cnt | x], Bcat = [W | root].
// 256 thr, block 128x128, thread tile 8m x 8n. KT=32 k-tiles:
//   B: cp.async double-buffered; A: LDG->regs prefetch (scaled by 1/cnt) -> STS.
template <bool LN>
__global__ __launch_bounds__(256)
void rgcn_gemm_kernel(const float* __restrict__ x,
                      const float* __restrict__ W,     // [R*128,128]
                      const float* __restrict__ root,  // [128,128]
                      const float* __restrict__ bias,
                      const float* __restrict__ gamma,
                      const float* __restrict__ beta,
                      float* __restrict__ out) {
    __shared__ float As[BM * KT];          // 16 KB
    __shared__ float Bs[2][KT * DIM];      // 32 KB

    int tid  = threadIdx.x;
    int row0 = blockIdx.x * BM;
    int ty   = tid >> 4;               // 0..15: rows ty*8..+7
    int tx   = tid & 15;               // cols tx*4..+3 and 64+tx*4..+3

    // A-prefetch indexing: 4 float4/thread; l-th covers row l*32 + (tid>>3), col4 = tid&7
    int arow_base = tid >> 3;
    int ac4       = tid & 7;
    // B cp.async indexing: 4 float4/thread; l-th covers brow l*8 + (tid>>5), col4 = tid&31
    int brow_base = tid >> 5;
    int bc4       = tid & 31;

    unsigned long long acc[8][4];
#pragma unroll
    for (int i = 0; i < 8; i++)
#pragma unroll
        for (int j = 0; j < 4; j++) acc[i][j] = 0ull;

    float4 rA[4];

    // ---- A tile loader (global -> regs, scaled) ----
    auto loadA = [&](int kt) {
        int kg0   = kt * KT;
        int chunk = kg0 >> 7;          // 0..8
        int kbase = kg0 & 127;
#pragma unroll
        for (int l = 0; l < 4; ++l) {
            int m  = l * 32 + arow_base;
            int gr = row0 + m;
            float4 v = make_float4(0.f, 0.f, 0.f, 0.f);
            if (gr < NNODES) {
                if (chunk < NREL) {
                    size_t seg = (size_t)gr * NREL + chunk;
                    float s = 1.0f / fmaxf(g_cnt[seg], 1.0f);
                    float4 t = *(const float4*)(g_agg + seg * DIM + kbase + ac4 * 4);
                    v.x = t.x * s; v.y = t.y * s; v.z = t.z * s; v.w = t.w * s;
                } else {
                    v = *(const float4*)(x + (size_t)gr * DIM + kbase + ac4 * 4);
                }
            }
            rA[l] = v;
        }
    };

    // ---- B tile cp.async issue ----
    auto issueB = [&](int kt, int buf) {
        int kg0 = kt * KT;
        const float* src = (kg0 < NREL * DIM)
                         ? (W + (size_t)kg0 * DIM)
                         : (root + (size_t)(kg0 - NREL * DIM) * DIM);
#pragma unroll
        for (int l = 0; l < 4; ++l) {
            int brow = l * 8 + brow_base;
            const float* g = src + (size_t)brow * DIM + bc4 * 4;
            unsigned saddr = (unsigned)__cvta_generic_to_shared(
                &Bs[buf][brow * DIM + bc4 * 4]);
            asm volatile("cp.async.cg.shared.global [%0], [%1], 16;"
                         :: "r"(saddr), "l"(g));
        }
        asm volatile("cp.async.commit_group;");
    };

    // ---- prologue ----
    loadA(0);
    issueB(0, 0);

#pragma unroll 1
    for (int kt = 0; kt < NKT; ++kt) {
        __syncthreads();               // previous tile's compute done reading As
        // store prefetched A
#pragma unroll
        for (int l = 0; l < 4; ++l)
            *(float4*)(As + (l * 32 + arow_base) * KT + ac4 * 4) = rA[l];
        if (kt + 1 < NKT) {
            issueB(kt + 1, (kt + 1) & 1);
            asm volatile("cp.async.wait_group 1;");   // B_kt landed
        } else {
            asm volatile("cp.async.wait_group 0;");
        }
        __syncthreads();               // As + Bs[kt&1] visible to all
        if (kt + 1 < NKT) loadA(kt + 1);   // long-latency, overlapped with compute

        const float* Bsb = Bs[kt & 1];
#pragma unroll 2
        for (int k4i = 0; k4i < KT / 4; ++k4i) {
            float4 af[8];
#pragma unroll
            for (int i = 0; i < 8; i++)
                af[i] = *(const float4*)(As + (ty * 8 + i) * KT + k4i * 4);
#pragma unroll
            for (int kk = 0; kk < 4; ++kk) {
                const float* brow = Bsb + (k4i * 4 + kk) * DIM;
                ulonglong2 b0 = *(const ulonglong2*)(brow + tx * 4);
                ulonglong2 b1 = *(const ulonglong2*)(brow + 64 + tx * 4);
                unsigned long long b[4] = {b0.x, b0.y, b1.x, b1.y};
#pragma unroll
                for (int i = 0; i < 8; i++) {
                    float a = (kk == 0) ? af[i].x : (kk == 1) ? af[i].y
                             : (kk == 2) ? af[i].z : af[i].w;
                    unsigned ai = __float_as_uint(a);
                    unsigned long long ad;
                    asm("mov.b64 %0, {%1,%1};" : "=l"(ad) : "r"(ai));
#pragma unroll
                    for (int j = 0; j < 4; j++)
                        asm("fma.rn.f32x2 %0, %1, %2, %0;"
                            : "+l"(acc[i][j]) : "l"(ad), "l"(b[j]));
                }
            }
        }
    }

    // ---- epilogue: bias + (LN+ReLU) fully in registers; row reduce over tx half-group ----
    float4 bv0 = *(const float4*)(bias + tx * 4);
    float4 bv1 = *(const float4*)(bias + 64 + tx * 4);
    float4 gm0, gm1, bt0, bt1;
    if (LN) {
        gm0 = *(const float4*)(gamma + tx * 4);
        gm1 = *(const float4*)(gamma + 64 + tx * 4);
        bt0 = *(const float4*)(beta + tx * 4);
        bt1 = *(const float4*)(beta + 64 + tx * 4);
    }
#pragma unroll
    for (int i = 0; i < 8; ++i) {
        int gr = row0 + ty * 8 + i;
        float r0[4], r1[4];
#pragma unroll
        for (int j = 0; j < 2; ++j) {
            r0[j * 2]     = __uint_as_float((unsigned)(acc[i][j] & 0xffffffffull));
            r0[j * 2 + 1] = __uint_as_float((unsigned)(acc[i][j] >> 32));
            r1[j * 2]     = __uint_as_float((unsigned)(acc[i][j + 2] & 0xffffffffull));
            r1[j * 2 + 1] = __uint_as_float((unsigned)(acc[i][j + 2] >> 32));
        }
        r0[0] += bv0.x; r0[1] += bv0.y; r0[2] += bv0.z; r0[3] += bv0.w;
        r1[0] += bv1.x; r1[1] += bv1.y; r1[2] += bv1.z; r1[3] += bv1.w;
        if (LN) {
            float s  = r0[0] + r0[1] + r0[2] + r0[3] + r1[0] + r1[1] + r1[2] + r1[3];
            float sq = r0[0]*r0[0] + r0[1]*r0[1] + r0[2]*r0[2] + r0[3]*r0[3]
                     + r1[0]*r1[0] + r1[1]*r1[1] + r1[2]*r1[2] + r1[3]*r1[3];
#pragma unroll
            for (int off = 8; off > 0; off >>= 1) {     // reduce across the 16 tx lanes
                s  += __shfl_xor_sync(0xffffffffu, s,  off);
                sq += __shfl_xor_sync(0xffffffffu, sq, off);
            }
            float mu  = s * (1.0f / DIM);
            float var = sq * (1.0f / DIM) - mu * mu;
            float inv = rsqrtf(var + LNEPS);
            float g0[4] = {gm0.x, gm0.y, gm0.z, gm0.w};
            float g1[4] = {gm1.x, gm1.y, gm1.z, gm1.w};
            float t0[4] = {bt0.x, bt0.y, bt0.z, bt0.w};
            float t1[4] = {bt1.x, bt1.y, bt1.z, bt1.w};
#pragma unroll
            for (int j = 0; j < 4; ++j) {
                r0[j] = fmaxf((r0[j] - mu) * inv * g0[j] + t0[j], 0.f);
                r1[j] = fmaxf((r1[j] - mu) * inv * g1[j] + t1[j], 0.f);
            }
        }
        if (gr < NNODES) {
            *(float4*)(out + (size_t)gr * DIM + tx * 4)      = make_float4(r0[0], r0[1], r0[2], r0[3]);
            *(float4*)(out + (size_t)gr * DIM + 64 + tx * 4) = make_float4(r1[0], r1[1], r1[2], r1[3]);
        }
    }
}

// ---------------- host side ----------------
static void run_layer(const float* xin, float* xout,
                      const float* W, const float* root, const float* bias,
                      const float* gamma, const float* beta, bool ln,
                      float* agg, float* cnt,
                      const int* edge_index, const int* edge_type) {
    const int agg4 = NNODES * NREL * DIM / 4;
    const int cnt4 = NNODES * NREL / 4;
    zero2_kernel<<<(agg4 + cnt4 + 255) / 256, 256>>>((float4*)agg, agg4, (float4*)cnt, cnt4);
    scatter_kernel<<<(NEDGES * 32 + 255) / 256, 256>>>(xin, edge_index, edge_type);
    int gblocks = (NNODES + BM - 1) / BM;
    if (ln)
        rgcn_gemm_kernel<true><<<gblocks, 256>>>(xin, W, root, bias, gamma, beta, xout);
    else
        rgcn_gemm_kernel<false><<<gblocks, 256>>>(xin, W, root, bias, nullptr, nullptr, xout);
}

extern "C" void kernel_launch(void* const* d_in, const int* in_sizes, int n_in,
                              void* d_out, int out_size) {
    const int*   node_ids   = (const int*)d_in[0];
    const int*   edge_index = (const int*)d_in[1];
    const int*   edge_type  = (const int*)d_in[2];
    const float* emb        = (const float*)d_in[3];
    const float* W1    = (const float*)d_in[4];
    const float* root1 = (const float*)d_in[5];
    const float* b1    = (const float*)d_in[6];
    const float* g1    = (const float*)d_in[7];
    const float* be1   = (const float*)d_in[8];
    const float* W2    = (const float*)d_in[9];
    const float* root2 = (const float*)d_in[10];
    const float* b2    = (const float*)d_in[11];
    const float* g2    = (const float*)d_in[12];
    const float* be2   = (const float*)d_in[13];
    const float* W3    = (const float*)d_in[14];
    const float* root3 = (const float*)d_in[15];
    const float* b3    = (const float*)d_in[16];
    float* out = (float*)d_out;

    float *xA, *xB, *agg, *cnt;
    cudaGetSymbolAddress((void**)&xA,  g_xA);
    cudaGetSymbolAddress((void**)&xB,  g_xB);
    cudaGetSymbolAddress((void**)&agg, g_agg);
    cudaGetSymbolAddress((void**)&cnt, g_cnt);

    // x0 = emb[node_ids]
    gather_kernel<<<(NNODES * 32 + 255) / 256, 256>>>(node_ids, (const float4*)emb, (float4*)xA);

    // layer 1: xA -> xB (LN+ReLU)
    run_layer(xA, xB, W1, root1, b1, g1, be1, true,  agg, cnt, edge_index, edge_type);
    // layer 2: xB -> xA (LN+ReLU)
    run_layer(xB, xA, W2, root2, b2, g2, be2, true,  agg, cnt, edge_index, edge_type);
    // layer 3: xA -> out (no LN)
    run_layer(xA, out, W3, root3, b3, nullptr, nullptr, false, agg, cnt, edge_index, edge_type);
}